// round 1
// baseline (speedup 1.0000x reference)
#include <cuda_runtime.h>

#define HW      64
#define CH      3
#define NPIX    (HW * HW)            // 4096
#define NELEM   (NPIX * CH)          // 12288 floats per image
#define THREADS 256
#define PPT     (NPIX / THREADS)     // 16 pixels per thread
#define SMEM_BYTES (NELEM * 4 + 128) // image + reduction scratch

__global__ void __launch_bounds__(THREADS)
dns_kernel(const float* __restrict__ images,
           const float* __restrict__ params,
           const float* __restrict__ kptr,
           float* __restrict__ out)
{
    extern __shared__ float smem[];
    float* red = smem;           // 32 floats scratch (only 16 used)
    float* img = smem + 32;      // NELEM floats, 128B-aligned

    const int b   = blockIdx.x;
    const int tid = threadIdx.x;
    const float* src = images + (size_t)b * NELEM;
    float*       dst = out    + (size_t)b * NELEM;

    // ---- stage image into SMEM (float4, fully coalesced) ----
    {
        const float4* s4 = (const float4*)src;
        float4*       i4 = (float4*)img;
        #pragma unroll
        for (int i = 0; i < (NELEM / 4) / THREADS; ++i)
            i4[tid + i * THREADS] = s4[tid + i * THREADS];
    }

    // ---- per-image parameters (uniform, cheap to recompute per thread) ----
    const float* p = params + b * 7;
    const float sigma_s = fminf(fmaxf(p[0], 0.2f), 5.0f);
    const float sigma_r = fminf(fmaxf(p[1], 0.01f), 1.0f);
    const float sigma_f = fminf(fmaxf(p[2], 0.2f), 3.0f);
    const float lam     = fminf(fmaxf(p[3], 0.1f), 2.0f);
    const float tau     = fminf(fmaxf(p[4], 0.5f), 5.0f);
    const float gain    = fminf(fmaxf(p[5], 0.2f), 2.0f);
    const float offset  = fminf(fmaxf(p[6], 0.01f), 1.0f);
    const float k_pos   = fmaxf(fabsf(*kptr), 1.0f);

    // 1D separable Gaussian weights: [e,1,e]/(1+2e)
    const float es  = __expf(-0.5f / (sigma_s * sigma_s));
    const float isn = 1.0f / (1.0f + 2.0f * es);
    const float ef  = __expf(-0.5f / (sigma_f * sigma_f));
    const float ifn = 1.0f / (1.0f + 2.0f * ef);
    const float sk[3] = { es * isn, isn, es * isn };
    const float fk[3] = { ef * ifn, ifn, ef * ifn };
    const float inv2s2   = -0.5f / (sigma_r * sigma_r);
    const float inv_tau2 = 1.0f / (tau * tau);

    __syncthreads();

    // ---- per-pixel compute; results kept in registers ----
    float res[PPT][CH];
    float sum_noise = 0.0f, sum_det = 0.0f;

    #pragma unroll
    for (int i = 0; i < PPT; ++i) {
        const int pidx = tid + i * THREADS;
        const int y = pidx >> 6, x = pidx & 63;
        // reflect padding (no edge repeat): -1 -> 1, 64 -> 62
        const int ys[3] = { (y == 0) ? 1 : y - 1, y, (y == 63) ? 62 : y + 1 };
        const int xs[3] = { (x == 0) ? 1 : x - 1, x, (x == 63) ? 62 : x + 1 };

        float cen0 = img[pidx * 3 + 0];
        float cen1 = img[pidx * 3 + 1];
        float cen2 = img[pidx * 3 + 2];

        float bn0 = 0.f, bn1 = 0.f, bn2 = 0.f, bden = 0.f;
        float gv0 = 0.f, gv1 = 0.f, gv2 = 0.f;

        #pragma unroll
        for (int dy = 0; dy < 3; ++dy) {
            const int rowb = ys[dy] * HW;
            #pragma unroll
            for (int dx = 0; dx < 3; ++dx) {
                const int q = (rowb + xs[dx]) * 3;
                const float n0 = img[q], n1 = img[q + 1], n2 = img[q + 2];
                const float d0 = n0 - cen0, d1 = n1 - cen1, d2 = n2 - cen2;
                const float cds = d0 * d0 + d1 * d1 + d2 * d2;
                const float kk  = (sk[dy] * sk[dx]) * __expf(inv2s2 * cds);
                bden += kk;
                bn0 += kk * n0; bn1 += kk * n1; bn2 += kk * n2;
                const float fw = fk[dy] * fk[dx];
                gv0 += fw * n0; gv1 += fw * n1; gv2 += fw * n2;
            }
        }
        const float inv_den = 1.0f / bden;

        const float cen[3] = { cen0, cen1, cen2 };
        const float bnum[3] = { bn0, bn1, bn2 };
        const float gval[3] = { gv0, gv1, gv2 };
        #pragma unroll
        for (int c = 0; c < CH; ++c) {
            const float bf     = bnum[c] * inv_den;
            const float detail = cen[c] - gval[c];
            const float ad     = fabsf(detail);
            const float denom  = fmaxf(cen[c] + offset, 1e-5f);
            const float ne     = fminf(ad * gain / denom, 10.0f);
            sum_noise += ne;
            sum_det   += ad;
            float ei = fmaxf(-(ne * ne) * inv_tau2, -88.0f);
            const float t1    = 1.0f - __expf(ei);
            const float nmask = t1 * t1;
            const float dmask = 1.0f / (1.0f + __expf(-k_pos * (ad - 0.002f)));
            res[i][c] = bf + lam * detail * nmask * dmask;
        }
    }

    // ---- block reduction for avg_noise / avg_detail ----
    #pragma unroll
    for (int o = 16; o > 0; o >>= 1) {
        sum_noise += __shfl_xor_sync(0xFFFFFFFFu, sum_noise, o);
        sum_det   += __shfl_xor_sync(0xFFFFFFFFu, sum_det, o);
    }
    if ((tid & 31) == 0) {
        red[tid >> 5]     = sum_noise;   // 8 warps
        red[8 + (tid >> 5)] = sum_det;
    }
    __syncthreads();
    float tn = 0.f, td = 0.f;
    #pragma unroll
    for (int w = 0; w < THREADS / 32; ++w) { tn += red[w]; td += red[8 + w]; }
    const float inv_n = 1.0f / (float)NELEM;
    const bool skip = (tn * inv_n < 1e-4f) || (td * inv_n < 1e-4f);

    // ---- final write (coalesced: contiguous 12B per thread) ----
    #pragma unroll
    for (int i = 0; i < PPT; ++i) {
        const int pidx = tid + i * THREADS;
        #pragma unroll
        for (int c = 0; c < CH; ++c) {
            float v = skip ? img[pidx * 3 + c] : res[i][c];
            v = fminf(fmaxf(v, 1e-5f), 1.0f);
            dst[pidx * 3 + c] = v;
        }
    }
}

extern "C" void kernel_launch(void* const* d_in, const int* in_sizes, int n_in,
                              void* d_out, int out_size)
{
    const float* images = (const float*)d_in[0];
    const float* params = (const float*)d_in[1];
    const float* kptr   = (const float*)d_in[2];
    float*       out    = (float*)d_out;

    const int nimg = in_sizes[1] / 7;  // B*P = 512

    cudaFuncSetAttribute(dns_kernel,
                         cudaFuncAttributeMaxDynamicSharedMemorySize, SMEM_BYTES);
    dns_kernel<<<nimg, THREADS, SMEM_BYTES>>>(images, params, kptr, out);
}

// round 2
// speedup vs baseline: 1.1484x; 1.1484x over previous
#include <cuda_runtime.h>

#define HW      64
#define CH      3
#define NPIX    (HW * HW)            // 4096
#define NELEM   (NPIX * CH)          // 12288 floats per image
#define THREADS 256
#define PPT     (NPIX / THREADS)     // 16 pixels per thread
#define SMEM_BYTES (NELEM * 4 + 128) // image + reduction scratch

__global__ void __launch_bounds__(THREADS, 4)
dns_kernel(const float* __restrict__ images,
           const float* __restrict__ params,
           const float* __restrict__ kptr,
           float* __restrict__ out)
{
    extern __shared__ float smem[];
    float* red = smem;           // 32 floats scratch (16 used)
    float* img = smem + 32;      // NELEM floats, 128B-aligned

    const int b   = blockIdx.x;
    const int tid = threadIdx.x;
    const float* src = images + (size_t)b * NELEM;
    float*       dst = out    + (size_t)b * NELEM;

    // ---- stage image into SMEM (float4, fully coalesced) ----
    {
        const float4* s4 = (const float4*)src;
        float4*       i4 = (float4*)img;
        #pragma unroll
        for (int i = 0; i < (NELEM / 4) / THREADS; ++i)
            i4[tid + i * THREADS] = s4[tid + i * THREADS];
    }

    // ---- per-image parameters (uniform across block) ----
    const float* p = params + b * 7;
    const float sigma_s = fminf(fmaxf(p[0], 0.2f), 5.0f);
    const float sigma_r = fminf(fmaxf(p[1], 0.01f), 1.0f);
    const float sigma_f = fminf(fmaxf(p[2], 0.2f), 3.0f);
    const float lam     = fminf(fmaxf(p[3], 0.1f), 2.0f);
    const float tau     = fminf(fmaxf(p[4], 0.5f), 5.0f);
    const float gain    = fminf(fmaxf(p[5], 0.2f), 2.0f);
    const float offset  = fminf(fmaxf(p[6], 0.01f), 1.0f);
    const float k_pos   = fmaxf(fabsf(*kptr), 1.0f);

    // 1D separable Gaussian weights: [e,1,e]/(1+2e)
    const float es  = __expf(-0.5f / (sigma_s * sigma_s));
    const float isn = __frcp_rn(1.0f + 2.0f * es);
    const float ef  = __expf(-0.5f / (sigma_f * sigma_f));
    const float ifn = __frcp_rn(1.0f + 2.0f * ef);
    const float sk[3] = { es * isn, isn, es * isn };
    const float fk[3] = { ef * ifn, ifn, ef * ifn };
    const float inv2s2   = -0.5f / (sigma_r * sigma_r);
    const float inv_tau2 = __frcp_rn(tau * tau);

    __syncthreads();

    // ---- per-pixel compute; speculative write of sharpened result ----
    float sum_noise = 0.0f, sum_det = 0.0f;

    #pragma unroll
    for (int i = 0; i < PPT; ++i) {
        const int pidx = tid + i * THREADS;
        const int y = pidx >> 6, x = pidx & 63;
        // reflect padding (no edge repeat): -1 -> 1, 64 -> 62
        const int ys[3] = { (y == 0) ? 1 : y - 1, y, (y == 63) ? 62 : y + 1 };
        const int xs[3] = { (x == 0) ? 1 : x - 1, x, (x == 63) ? 62 : x + 1 };

        const float cen0 = img[pidx * 3 + 0];
        const float cen1 = img[pidx * 3 + 1];
        const float cen2 = img[pidx * 3 + 2];

        float bn0 = 0.f, bn1 = 0.f, bn2 = 0.f, bden = 0.f;
        float gv0 = 0.f, gv1 = 0.f, gv2 = 0.f;

        #pragma unroll
        for (int dy = 0; dy < 3; ++dy) {
            const int rowb = ys[dy] * HW;
            #pragma unroll
            for (int dx = 0; dx < 3; ++dx) {
                const int q = (rowb + xs[dx]) * 3;
                const float n0 = img[q], n1 = img[q + 1], n2 = img[q + 2];
                const float d0 = n0 - cen0, d1 = n1 - cen1, d2 = n2 - cen2;
                const float cds = d0 * d0 + d1 * d1 + d2 * d2;
                const float kk  = (sk[dy] * sk[dx]) * __expf(inv2s2 * cds);
                bden += kk;
                bn0 += kk * n0; bn1 += kk * n1; bn2 += kk * n2;
                const float fw = fk[dy] * fk[dx];
                gv0 += fw * n0; gv1 += fw * n1; gv2 += fw * n2;
            }
        }
        const float inv_den = __frcp_rn(bden);

        const float cen[3]  = { cen0, cen1, cen2 };
        const float bnum[3] = { bn0, bn1, bn2 };
        const float gval[3] = { gv0, gv1, gv2 };
        #pragma unroll
        for (int c = 0; c < CH; ++c) {
            const float bf     = bnum[c] * inv_den;
            const float detail = cen[c] - gval[c];
            const float ad     = fabsf(detail);
            const float denom  = fmaxf(cen[c] + offset, 1e-5f);
            const float ne     = fminf(__fdividef(ad * gain, denom), 10.0f);
            sum_noise += ne;
            sum_det   += ad;
            const float ei    = fmaxf(-(ne * ne) * inv_tau2, -88.0f);
            const float t1    = 1.0f - __expf(ei);
            const float nmask = t1 * t1;
            const float dmask = __frcp_rn(1.0f + __expf(-k_pos * (ad - 0.002f)));
            const float v     = bf + lam * detail * nmask * dmask;
            dst[pidx * 3 + c] = fminf(fmaxf(v, 1e-5f), 1.0f);
        }
    }

    // ---- block reduction for avg_noise / avg_detail ----
    #pragma unroll
    for (int o = 16; o > 0; o >>= 1) {
        sum_noise += __shfl_xor_sync(0xFFFFFFFFu, sum_noise, o);
        sum_det   += __shfl_xor_sync(0xFFFFFFFFu, sum_det, o);
    }
    if ((tid & 31) == 0) {
        red[tid >> 5]       = sum_noise;   // 8 warps
        red[8 + (tid >> 5)] = sum_det;
    }
    __syncthreads();
    float tn = 0.f, td = 0.f;
    #pragma unroll
    for (int w = 0; w < THREADS / 32; ++w) { tn += red[w]; td += red[8 + w]; }
    const float inv_n = 1.0f / (float)NELEM;
    const bool skip = (tn * inv_n < 1e-4f) || (td * inv_n < 1e-4f);

    // ---- rare path: image should be skipped -> overwrite with clip(x) ----
    if (skip) {
        #pragma unroll
        for (int i = 0; i < PPT; ++i) {
            const int pidx = tid + i * THREADS;
            #pragma unroll
            for (int c = 0; c < CH; ++c) {
                const float v = img[pidx * 3 + c];
                dst[pidx * 3 + c] = fminf(fmaxf(v, 1e-5f), 1.0f);
            }
        }
    }
}

extern "C" void kernel_launch(void* const* d_in, const int* in_sizes, int n_in,
                              void* d_out, int out_size)
{
    const float* images = (const float*)d_in[0];
    const float* params = (const float*)d_in[1];
    const float* kptr   = (const float*)d_in[2];
    float*       out    = (float*)d_out;

    const int nimg = in_sizes[1] / 7;  // B*P = 512

    cudaFuncSetAttribute(dns_kernel,
                         cudaFuncAttributeMaxDynamicSharedMemorySize, SMEM_BYTES);
    dns_kernel<<<nimg, THREADS, SMEM_BYTES>>>(images, params, kptr, out);
}

// round 3
// speedup vs baseline: 1.1633x; 1.0130x over previous
#include <cuda_runtime.h>

#define HW      64
#define CH      3
#define NPIX    (HW * HW)            // 4096
#define NELEM   (NPIX * CH)          // 12288 floats per image
#define THREADS 512
#define NWARP   (THREADS / 32)       // 16
#define PPT     (NPIX / THREADS)     // 8 pixels per thread
#define SMEM_BYTES (NELEM * 4 + 256) // image + reduction scratch

__global__ void __launch_bounds__(THREADS, 3)
dns_kernel(const float* __restrict__ images,
           const float* __restrict__ params,
           const float* __restrict__ kptr,
           float* __restrict__ out)
{
    extern __shared__ float smem[];
    float* red = smem;           // 64 floats scratch (32 used)
    float* img = smem + 64;      // NELEM floats, 256B-aligned

    const int b   = blockIdx.x;
    const int tid = threadIdx.x;
    const float* src = images + (size_t)b * NELEM;
    float*       dst = out    + (size_t)b * NELEM;

    // ---- stage image into SMEM (float4, fully coalesced) ----
    {
        const float4* s4 = (const float4*)src;
        float4*       i4 = (float4*)img;
        #pragma unroll
        for (int i = 0; i < (NELEM / 4) / THREADS; ++i)
            i4[tid + i * THREADS] = s4[tid + i * THREADS];
    }

    // ---- per-image parameters (uniform across block) ----
    const float* p = params + b * 7;
    const float sigma_s = fminf(fmaxf(p[0], 0.2f), 5.0f);
    const float sigma_r = fminf(fmaxf(p[1], 0.01f), 1.0f);
    const float sigma_f = fminf(fmaxf(p[2], 0.2f), 3.0f);
    const float lam     = fminf(fmaxf(p[3], 0.1f), 2.0f);
    const float tau     = fminf(fmaxf(p[4], 0.5f), 5.0f);
    const float gain    = fminf(fmaxf(p[5], 0.2f), 2.0f);
    const float offset  = fminf(fmaxf(p[6], 0.01f), 1.0f);
    const float k_pos   = fmaxf(fabsf(*kptr), 1.0f);

    // 1D separable Gaussian weights: [e,1,e]/(1+2e)
    const float es  = __expf(-0.5f / (sigma_s * sigma_s));
    const float isn = __frcp_rn(1.0f + 2.0f * es);
    const float ef  = __expf(-0.5f / (sigma_f * sigma_f));
    const float ifn = __frcp_rn(1.0f + 2.0f * ef);
    const float sk[3] = { es * isn, isn, es * isn };
    const float fk[3] = { ef * ifn, ifn, ef * ifn };
    const float inv2s2   = -0.5f / (sigma_r * sigma_r);
    const float inv_tau2 = __frcp_rn(tau * tau);

    __syncthreads();

    // ---- per-pixel compute; speculative write of sharpened result ----
    float sum_noise = 0.0f, sum_det = 0.0f;

    #pragma unroll
    for (int i = 0; i < PPT; ++i) {
        const int pidx = tid + i * THREADS;
        const int y = pidx >> 6, x = pidx & 63;
        // reflect padding (no edge repeat): -1 -> 1, 64 -> 62
        const int ys[3] = { (y == 0) ? 1 : y - 1, y, (y == 63) ? 62 : y + 1 };
        const int xs[3] = { (x == 0) ? 1 : x - 1, x, (x == 63) ? 62 : x + 1 };

        const float cen0 = img[pidx * 3 + 0];
        const float cen1 = img[pidx * 3 + 1];
        const float cen2 = img[pidx * 3 + 2];

        float bn0 = 0.f, bn1 = 0.f, bn2 = 0.f, bden = 0.f;
        float gv0 = 0.f, gv1 = 0.f, gv2 = 0.f;

        #pragma unroll
        for (int dy = 0; dy < 3; ++dy) {
            const int rowb = ys[dy] * HW;
            const float sky = sk[dy], fky = fk[dy];
            #pragma unroll
            for (int dx = 0; dx < 3; ++dx) {
                const int q = (rowb + xs[dx]) * 3;
                const float n0 = img[q], n1 = img[q + 1], n2 = img[q + 2];
                const float d0 = n0 - cen0, d1 = n1 - cen1, d2 = n2 - cen2;
                const float cds = d0 * d0 + d1 * d1 + d2 * d2;
                const float kk  = (sky * sk[dx]) * __expf(inv2s2 * cds);
                bden += kk;
                bn0 += kk * n0; bn1 += kk * n1; bn2 += kk * n2;
                const float fw = fky * fk[dx];
                gv0 += fw * n0; gv1 += fw * n1; gv2 += fw * n2;
            }
        }
        const float inv_den = __frcp_rn(bden);

        const float cen[3]  = { cen0, cen1, cen2 };
        const float bnum[3] = { bn0, bn1, bn2 };
        const float gval[3] = { gv0, gv1, gv2 };
        #pragma unroll
        for (int c = 0; c < CH; ++c) {
            const float bf     = bnum[c] * inv_den;
            const float detail = cen[c] - gval[c];
            const float ad     = fabsf(detail);
            const float denom  = fmaxf(cen[c] + offset, 1e-5f);
            const float ne     = fminf(__fdividef(ad * gain, denom), 10.0f);
            sum_noise += ne;
            sum_det   += ad;
            const float ei    = fmaxf(-(ne * ne) * inv_tau2, -88.0f);
            const float t1    = 1.0f - __expf(ei);
            const float nmask = t1 * t1;
            const float dmask = __frcp_rn(1.0f + __expf(-k_pos * (ad - 0.002f)));
            const float v     = bf + lam * detail * nmask * dmask;
            dst[pidx * 3 + c] = fminf(fmaxf(v, 1e-5f), 1.0f);
        }
    }

    // ---- block reduction for avg_noise / avg_detail ----
    #pragma unroll
    for (int o = 16; o > 0; o >>= 1) {
        sum_noise += __shfl_xor_sync(0xFFFFFFFFu, sum_noise, o);
        sum_det   += __shfl_xor_sync(0xFFFFFFFFu, sum_det, o);
    }
    if ((tid & 31) == 0) {
        red[tid >> 5]           = sum_noise;   // 16 warps
        red[NWARP + (tid >> 5)] = sum_det;
    }
    __syncthreads();
    float tn = 0.f, td = 0.f;
    #pragma unroll
    for (int w = 0; w < NWARP; ++w) { tn += red[w]; td += red[NWARP + w]; }
    const float inv_n = 1.0f / (float)NELEM;
    const bool skip = (tn * inv_n < 1e-4f) || (td * inv_n < 1e-4f);

    // ---- rare path: image should be skipped -> overwrite with clip(x) ----
    if (skip) {
        #pragma unroll
        for (int i = 0; i < PPT; ++i) {
            const int pidx = tid + i * THREADS;
            #pragma unroll
            for (int c = 0; c < CH; ++c) {
                const float v = img[pidx * 3 + c];
                dst[pidx * 3 + c] = fminf(fmaxf(v, 1e-5f), 1.0f);
            }
        }
    }
}

extern "C" void kernel_launch(void* const* d_in, const int* in_sizes, int n_in,
                              void* d_out, int out_size)
{
    const float* images = (const float*)d_in[0];
    const float* params = (const float*)d_in[1];
    const float* kptr   = (const float*)d_in[2];
    float*       out    = (float*)d_out;

    const int nimg = in_sizes[1] / 7;  // B*P = 512

    cudaFuncSetAttribute(dns_kernel,
                         cudaFuncAttributeMaxDynamicSharedMemorySize, SMEM_BYTES);
    dns_kernel<<<nimg, THREADS, SMEM_BYTES>>>(images, params, kptr, out);
}

// round 4
// speedup vs baseline: 1.4672x; 1.2613x over previous
#include <cuda_runtime.h>

#define HW      64
#define CH      3
#define NPIX    (HW * HW)            // 4096
#define NELEM   (NPIX * CH)          // 12288 floats per image
#define THREADS 512
#define NWARP   (THREADS / 32)       // 16
#define PPT     (NPIX / THREADS)     // 8 pixels per thread
// float4-per-pixel image plane + reduction scratch
#define SMEM_BYTES (NPIX * 16 + 256)
#define LOG2E 1.4426950408889634f

__device__ __forceinline__ float ex2f(float x) {
    float r; asm("ex2.approx.ftz.f32 %0, %1;" : "=f"(r) : "f"(x)); return r;
}
__device__ __forceinline__ float rcpf(float x) {
    float r; asm("rcp.approx.ftz.f32 %0, %1;" : "=f"(r) : "f"(x)); return r;
}

__global__ void __launch_bounds__(THREADS, 3)
dns_kernel(const float* __restrict__ images,
           const float* __restrict__ params,
           const float* __restrict__ kptr,
           float* __restrict__ out)
{
    extern __shared__ float smem[];
    float*  red  = smem;            // 64 floats scratch
    float*  img  = smem + 64;       // NPIX * 4 floats (float4 per pixel)
    float4* img4 = (float4*)img;

    const int b   = blockIdx.x;
    const int tid = threadIdx.x;
    const float* src = images + (size_t)b * NELEM;
    float*       dst = out    + (size_t)b * NELEM;

    // ---- stage image: coalesced float4 gmem reads, scatter into padded smem ----
    {
        const float4* s4 = (const float4*)src;
        #pragma unroll
        for (int j = 0; j < (NELEM / 4) / THREADS; ++j) {
            const int   wbase = (tid + j * THREADS) * 4;
            const float4 v = s4[tid + j * THREADS];
            const float  w[4] = { v.x, v.y, v.z, v.w };
            #pragma unroll
            for (int k = 0; k < 4; ++k) {
                const int widx = wbase + k;
                const int pix  = widx / 3;
                const int ch   = widx - pix * 3;
                img[pix * 4 + ch] = w[k];
            }
        }
    }

    // ---- per-image parameters (uniform across block) ----
    const float* p = params + b * 7;
    const float sigma_s = fminf(fmaxf(p[0], 0.2f), 5.0f);
    const float sigma_r = fminf(fmaxf(p[1], 0.01f), 1.0f);
    const float sigma_f = fminf(fmaxf(p[2], 0.2f), 3.0f);
    const float lam     = fminf(fmaxf(p[3], 0.1f), 2.0f);
    const float tau     = fminf(fmaxf(p[4], 0.5f), 5.0f);
    const float gain    = fminf(fmaxf(p[5], 0.2f), 2.0f);
    const float offset  = fminf(fmaxf(p[6], 0.01f), 1.0f);
    const float k_pos   = fmaxf(fabsf(*kptr), 1.0f);

    // bilateral: spatial weight folded into exp arg (log2 units); isn^2 cancels in bf
    const float ls2      = (-0.5f / (sigma_s * sigma_s)) * LOG2E; // log2(es)
    const float b_edge   = ls2;
    const float b_corner = 2.0f * ls2;
    const float cR       = (-0.5f / (sigma_r * sigma_r)) * LOG2E;

    // gaussian (separable, e-factored): gf = ifn2*(C + ef*e4 + ef2*c4)
    const float ef   = __expf(-0.5f / (sigma_f * sigma_f));
    const float ef2  = ef * ef;
    const float ifn  = rcpf(1.0f + 2.0f * ef);
    const float ifn2 = ifn * ifn;

    const float invtau2L2 = rcpf(tau * tau) * LOG2E;   // for ex2(-ne^2 * this)
    const float kL2       = k_pos * LOG2E;             // sigmoid in log2 units

    __syncthreads();

    float sum_noise = 0.0f, sum_det = 0.0f;

    #pragma unroll
    for (int i = 0; i < PPT; ++i) {
        const int pidx = tid + i * THREADS;
        const int y = pidx >> 6, x = pidx & 63;
        // reflect (no edge repeat) via abs tricks
        const int ym = abs(y - 1);
        const int yp = 63 - abs(62 - y);
        const int xm = abs(x - 1);
        const int xp = 63 - abs(62 - x);
        const int r0 = y  * HW, rm = ym * HW, rp = yp * HW;

        const float4 C = img4[r0 + x];

        float bn0 = C.x, bn1 = C.y, bn2 = C.z, bden = 1.0f; // center tap: kk=1
        float e40 = 0.f, e41 = 0.f, e42 = 0.f;              // edge sums
        float c40 = 0.f, c41 = 0.f, c42 = 0.f;              // corner sums

        #define TAP(IDX, BIAS, ACC0, ACC1, ACC2)                              \
        {                                                                      \
            const float4 t = img4[IDX];                                        \
            const float d0 = t.x - C.x, d1 = t.y - C.y, d2 = t.z - C.z;        \
            const float cds = d0 * d0 + d1 * d1 + d2 * d2;                     \
            const float kk = ex2f(fmaf(cds, cR, BIAS));                        \
            bden += kk;                                                        \
            bn0 = fmaf(kk, t.x, bn0);                                          \
            bn1 = fmaf(kk, t.y, bn1);                                          \
            bn2 = fmaf(kk, t.z, bn2);                                          \
            ACC0 += t.x; ACC1 += t.y; ACC2 += t.z;                             \
        }

        TAP(rm + x,  b_edge,   e40, e41, e42)   // up
        TAP(rp + x,  b_edge,   e40, e41, e42)   // down
        TAP(r0 + xm, b_edge,   e40, e41, e42)   // left
        TAP(r0 + xp, b_edge,   e40, e41, e42)   // right
        TAP(rm + xm, b_corner, c40, c41, c42)   // corners
        TAP(rm + xp, b_corner, c40, c41, c42)
        TAP(rp + xm, b_corner, c40, c41, c42)
        TAP(rp + xp, b_corner, c40, c41, c42)
        #undef TAP

        const float inv_den = rcpf(bden);

        const float cen[3]  = { C.x, C.y, C.z };
        const float bnum[3] = { bn0, bn1, bn2 };
        const float gr[3]   = { fmaf(ef, e40, fmaf(ef2, c40, C.x)),
                                fmaf(ef, e41, fmaf(ef2, c41, C.y)),
                                fmaf(ef, e42, fmaf(ef2, c42, C.z)) };
        #pragma unroll
        for (int c = 0; c < CH; ++c) {
            const float bf     = bnum[c] * inv_den;
            const float detail = fmaf(-ifn2, gr[c], cen[c]);  // cen - ifn2*graw
            const float ad     = fabsf(detail);
            const float denom  = fmaxf(cen[c] + offset, 1e-5f);
            const float ne     = fminf(ad * gain * rcpf(denom), 10.0f);
            sum_noise += ne;
            sum_det   += ad;
            const float em    = ex2f(-(ne * ne) * invtau2L2);  // underflows to 0 ok
            const float t1    = 1.0f - em;
            const float nmask = t1 * t1;
            const float dmask = rcpf(1.0f + ex2f(-kL2 * (ad - 0.002f)));
            const float v     = fmaf(lam * detail, nmask * dmask, bf);
            dst[pidx * 3 + c] = fminf(fmaxf(v, 1e-5f), 1.0f);
        }
    }

    // ---- block reduction for avg_noise / avg_detail ----
    #pragma unroll
    for (int o = 16; o > 0; o >>= 1) {
        sum_noise += __shfl_xor_sync(0xFFFFFFFFu, sum_noise, o);
        sum_det   += __shfl_xor_sync(0xFFFFFFFFu, sum_det, o);
    }
    if ((tid & 31) == 0) {
        red[tid >> 5]           = sum_noise;
        red[NWARP + (tid >> 5)] = sum_det;
    }
    __syncthreads();
    float tn = 0.f, td = 0.f;
    #pragma unroll
    for (int w = 0; w < NWARP; ++w) { tn += red[w]; td += red[NWARP + w]; }
    const float inv_n = 1.0f / (float)NELEM;
    const bool skip = (tn * inv_n < 1e-4f) || (td * inv_n < 1e-4f);

    // ---- rare path: overwrite with clip(x) ----
    if (skip) {
        #pragma unroll
        for (int i = 0; i < PPT; ++i) {
            const int pidx = tid + i * THREADS;
            const float4 C = img4[pidx];
            const float w[3] = { C.x, C.y, C.z };
            #pragma unroll
            for (int c = 0; c < CH; ++c)
                dst[pidx * 3 + c] = fminf(fmaxf(w[c], 1e-5f), 1.0f);
        }
    }
}

extern "C" void kernel_launch(void* const* d_in, const int* in_sizes, int n_in,
                              void* d_out, int out_size)
{
    const float* images = (const float*)d_in[0];
    const float* params = (const float*)d_in[1];
    const float* kptr   = (const float*)d_in[2];
    float*       out    = (float*)d_out;

    const int nimg = in_sizes[1] / 7;  // B*P = 512

    cudaFuncSetAttribute(dns_kernel,
                         cudaFuncAttributeMaxDynamicSharedMemorySize, SMEM_BYTES);
    dns_kernel<<<nimg, THREADS, SMEM_BYTES>>>(images, params, kptr, out);
}